// round 15
// baseline (speedup 1.0000x reference)
#include <cuda_runtime.h>
#include <cuda_fp16.h>
#include <cstdint>

#define D     512
#define NTR   16384
#define NT    8192
#define NCLS  16

#define SCHUNK   256                 // j per staged chunk
#define NSCU     4                   // chunks per attn unit (1024 j)
#define MTILE    64                  // i rows per attn unit (4 warps x 16)
#define YSTR     24                  // halves per padded ytr row (48B, conflict-free ldmatrix)
#define NSLOT    16                  // partial slots: (split, half)

#define LOG2E  1.4426950408889634f
#define MS2    (-8.656170245333781f)   // -6 nats in log2 units, softmax-invariant shift

// ---- ticket queue ----
#define NPROD    128                 // producer tickets (stagger chunks in order)
#define TATT     2048                // attn units: (x, split, half)
#define NTICK    (NPROD + TATT)
#define GRID_FUSED 1036              // 7 CTAs/SM x 148 SMs — ALL resident (deadlock-free)

// ---------------- device scratch ----------------
__device__ float2 g_q[NT];
__device__ float2 g_k[NTR];
__device__ uint4  g_y16[NTR * 2];
__device__ float  g_pnum[NSLOT * NT * NCLS];
__device__ float  g_pden[NSLOT * NT];
__device__ int    g_ticket;          // reset by reduce_kernel each launch
__device__ int    g_qrdy[NPROD];     // per-64-row q block ready flags
__device__ int    g_ccnt[64];        // per-chunk completion counts (target NPROD)

// ---------------- helpers ----------------
__device__ __forceinline__ float ex2f(float x) {
    float r; asm("ex2.approx.ftz.f32 %0, %1;" : "=f"(r) : "f"(x)); return r;
}
__device__ __forceinline__ uint32_t cvt_f16x2(float hi, float lo) {
    uint32_t r; asm("cvt.rn.f16x2.f32 %0, %1, %2;" : "=r"(r) : "f"(hi), "f"(lo)); return r;
}
__device__ __forceinline__ uint32_t smem_u32(const void* p) {
    uint32_t a;
    asm("{ .reg .u64 t; cvta.to.shared.u64 t, %1; cvt.u32.u64 %0, t; }" : "=r"(a) : "l"(p));
    return a;
}
__device__ __forceinline__ void ldmatrix_x4_trans(uint32_t& r0, uint32_t& r1,
                                                  uint32_t& r2, uint32_t& r3,
                                                  uint32_t addr) {
    asm volatile("ldmatrix.sync.aligned.m8n8.x4.trans.shared.b16 {%0,%1,%2,%3}, [%4];"
                 : "=r"(r0), "=r"(r1), "=r"(r2), "=r"(r3) : "r"(addr));
}
__device__ __forceinline__ void mma16816(float& c0, float& c1, float& c2, float& c3,
                                         uint32_t a0, uint32_t a1, uint32_t a2, uint32_t a3,
                                         uint32_t b0, uint32_t b1) {
    asm volatile("mma.sync.aligned.m16n8k16.row.col.f32.f16.f16.f32 "
                 "{%0,%1,%2,%3}, {%4,%5,%6,%7}, {%8,%9}, {%0,%1,%2,%3};"
                 : "+f"(c0), "+f"(c1), "+f"(c2), "+f"(c3)
                 : "r"(a0), "r"(a1), "r"(a2), "r"(a3), "r"(b0), "r"(b1));
}
__device__ __forceinline__ void spin_until(volatile int* p, int target) {
    if (*p < target) {
        while (*p < target) __nanosleep(64);
    }
}

// one-row projection by one warp, A held in registers (round-8 math)
__device__ __forceinline__ void proj_row_warp(const float* __restrict__ xrow,
                                              float2* dst, int drow, float scale,
                                              const float* a0, const float* a1, int lane) {
    const float4* xr4 = reinterpret_cast<const float4*>(xrow);
    float4 x0 = xr4[lane];
    float4 x1 = xr4[32 + lane];
    float4 x2 = xr4[64 + lane];
    float4 x3 = xr4[96 + lane];

    float s0, s1;
    s0 =      x0.x * a0[0];            s1 =      x0.x * a1[0];
    s0 = fmaf(x0.y, a0[1],  s0);       s1 = fmaf(x0.y, a1[1],  s1);
    s0 = fmaf(x0.z, a0[2],  s0);       s1 = fmaf(x0.z, a1[2],  s1);
    s0 = fmaf(x0.w, a0[3],  s0);       s1 = fmaf(x0.w, a1[3],  s1);
    s0 = fmaf(x1.x, a0[4],  s0);       s1 = fmaf(x1.x, a1[4],  s1);
    s0 = fmaf(x1.y, a0[5],  s0);       s1 = fmaf(x1.y, a1[5],  s1);
    s0 = fmaf(x1.z, a0[6],  s0);       s1 = fmaf(x1.z, a1[6],  s1);
    s0 = fmaf(x1.w, a0[7],  s0);       s1 = fmaf(x1.w, a1[7],  s1);
    s0 = fmaf(x2.x, a0[8],  s0);       s1 = fmaf(x2.x, a1[8],  s1);
    s0 = fmaf(x2.y, a0[9],  s0);       s1 = fmaf(x2.y, a1[9],  s1);
    s0 = fmaf(x2.z, a0[10], s0);       s1 = fmaf(x2.z, a1[10], s1);
    s0 = fmaf(x2.w, a0[11], s0);       s1 = fmaf(x2.w, a1[11], s1);
    s0 = fmaf(x3.x, a0[12], s0);       s1 = fmaf(x3.x, a1[12], s1);
    s0 = fmaf(x3.y, a0[13], s0);       s1 = fmaf(x3.y, a1[13], s1);
    s0 = fmaf(x3.z, a0[14], s0);       s1 = fmaf(x3.z, a1[14], s1);
    s0 = fmaf(x3.w, a0[15], s0);       s1 = fmaf(x3.w, a1[15], s1);

    #pragma unroll
    for (int off = 16; off > 0; off >>= 1) {
        s0 += __shfl_xor_sync(0xFFFFFFFFu, s0, off);
        s1 += __shfl_xor_sync(0xFFFFFFFFu, s1, off);
    }
    if (lane == 0) dst[drow] = make_float2(s0 * scale, s1 * scale);
}

// ---------------- fused persistent kernel ----------------
__global__ __launch_bounds__(128, 7) void fused_kernel(const float* __restrict__ xtr,
                                                       const float* __restrict__ ytr,
                                                       const float* __restrict__ xt,
                                                       const float* __restrict__ A) {
    __shared__ __align__(16) float2 sk[2][SCHUNK];         // 4KB
    __shared__ __align__(16) __half sy[2][SCHUNK * YSTR];  // 24KB
    __shared__ int s_t;

    int tid  = threadIdx.x;
    int warp = tid >> 5;
    int lane = tid & 31;

    for (;;) {
        __syncthreads();                 // protects s_t (write-after-read)
        if (tid == 0) s_t = atomicAdd(&g_ticket, 1);
        __syncthreads();
        int t = s_t;
        if (t >= NTICK) break;

        if (t < NPROD) {
            // ======== producer ticket p: q block, then staggered chunk slices ========
            int p = t;

            // A slice -> registers (global, L2-resident, coalesced)
            float a0[16], a1[16];
            const float4* A4 = reinterpret_cast<const float4*>(A);
            #pragma unroll
            for (int it = 0; it < 4; it++) {
                float4 v0 = A4[it * 64 + lane * 2];
                float4 v1 = A4[it * 64 + lane * 2 + 1];
                a0[it * 4 + 0] = v0.x;  a1[it * 4 + 0] = v0.y;
                a0[it * 4 + 1] = v0.z;  a1[it * 4 + 1] = v0.w;
                a0[it * 4 + 2] = v1.x;  a1[it * 4 + 2] = v1.y;
                a0[it * 4 + 3] = v1.z;  a1[it * 4 + 3] = v1.w;
            }

            // --- q block p: 64 rows (16 per warp) ---
            {
                int qb = p * 64 + warp * 16;
                for (int r = 0; r < 16; r++)
                    proj_row_warp(xt + (size_t)(qb + r) * D, g_q, qb + r, LOG2E, a0, a1, lane);
                __threadfence();
                __syncthreads();
                if (tid == 0) g_qrdy[p] = 1;
            }

            // --- chunk-pair loop: this producer's 2 rows of every chunk, in order ---
            for (int cc = 0; cc < 32; cc++) {
                int c    = cc * 2 + (warp & 1);
                int row  = c * 256 + p * 2 + (warp >> 1);
                proj_row_warp(xtr + (size_t)row * D, g_k, row, 1.0f, a0, a1, lane);
                if (lane < 2) {
                    const float4* ys = reinterpret_cast<const float4*>(ytr + (size_t)row * NCLS);
                    float4 u0 = ys[lane * 2], u1 = ys[lane * 2 + 1];
                    uint4 o;
                    o.x = cvt_f16x2(u0.y, u0.x); o.y = cvt_f16x2(u0.w, u0.z);
                    o.z = cvt_f16x2(u1.y, u1.x); o.w = cvt_f16x2(u1.w, u1.z);
                    g_y16[row * 2 + lane] = o;
                }
                __threadfence();
                __syncthreads();
                if (tid == 0) {
                    atomicAdd(&g_ccnt[cc * 2], 1);
                    atomicAdd(&g_ccnt[cc * 2 + 1], 1);
                }
            }
        } else {
            // ======== attn unit: (x, split, half), 64 i-rows x 1024 j ========
            int a    = t - NPROD;
            int s    = a >> 8;
            int rr   = a & 255;
            int x    = rr >> 1;
            int half = rr & 1;
            int cb   = s * 8 + half * 4;
            int j0   = s * 2048 + half * 1024;

            if (tid == 0) {
                spin_until(&g_qrdy[x], 1);
                spin_until(&g_ccnt[cb], NPROD);
                spin_until(&g_ccnt[cb + 1], NPROD);
                __threadfence();
            }
            __syncthreads();

            int g  = lane >> 2;
            int tg = lane & 3;
            int r0 = x * MTILE + warp * 16 + g;
            int r1 = r0 + 8;
            float2 qg = g_q[r0];
            float2 qh = g_q[r1];

            float d10 = 0, d11 = 0, d12 = 0, d13 = 0;
            float d20 = 0, d21 = 0, d22 = 0, d23 = 0;
            float e0 = 0, e1 = 0, e2 = 0, e3 = 0;
            const uint32_t ONES = 0x3C003C00u;

            float4 pk;  uint4 py0, py1, py2, py3;

#define LDG_CHUNK(sc) do {                                                   \
            int jb = j0 + (sc) * SCHUNK;                                     \
            pk = reinterpret_cast<const float4*>(g_k)[(jb >> 1) + tid];      \
            int rr2 = (jb + 2 * tid) * 2;                                    \
            py0 = g_y16[rr2]; py1 = g_y16[rr2 + 1];                          \
            py2 = g_y16[rr2 + 2]; py3 = g_y16[rr2 + 3];                      \
        } while (0)

#define STS_CHUNK(b) do {                                                    \
            reinterpret_cast<float4*>(sk[b])[tid] = pk;                      \
            uint4* dr0 = reinterpret_cast<uint4*>(&sy[b][(2 * tid) * YSTR]); \
            dr0[0] = py0; dr0[1] = py1;                                      \
            uint4* dr1 = reinterpret_cast<uint4*>(&sy[b][(2 * tid + 1) * YSTR]); \
            dr1[0] = py2; dr1[1] = py3;                                      \
        } while (0)

            LDG_CHUNK(0);
            STS_CHUNK(0);
            LDG_CHUNK(1);
            __syncthreads();

            for (int sc = 0; sc < NSCU; sc++) {
                int b = sc & 1;
                const float4* k4 = reinterpret_cast<const float4*>(sk[b]);
                uint32_t ybase = smem_u32(&sy[b][(lane & 15) * YSTR]) + (lane >> 4) * 16;

                #pragma unroll 4
                for (int ks = 0; ks < SCHUNK / 16; ks++) {
                    float4 ka = k4[ks * 8 + tg];
                    float4 kb = k4[ks * 8 + 4 + tg];

                    float wg0 = ex2f(fmaf(qg.x, ka.x, fmaf(qg.y, ka.y, MS2)));
                    float wg1 = ex2f(fmaf(qg.x, ka.z, fmaf(qg.y, ka.w, MS2)));
                    float wg2 = ex2f(fmaf(qg.x, kb.x, fmaf(qg.y, kb.y, MS2)));
                    float wg3 = ex2f(fmaf(qg.x, kb.z, fmaf(qg.y, kb.w, MS2)));
                    float wh0 = ex2f(fmaf(qh.x, ka.x, fmaf(qh.y, ka.y, MS2)));
                    float wh1 = ex2f(fmaf(qh.x, ka.z, fmaf(qh.y, ka.w, MS2)));
                    float wh2 = ex2f(fmaf(qh.x, kb.x, fmaf(qh.y, kb.y, MS2)));
                    float wh3 = ex2f(fmaf(qh.x, kb.z, fmaf(qh.y, kb.w, MS2)));

                    uint32_t a0 = cvt_f16x2(wg1, wg0);
                    uint32_t a1 = cvt_f16x2(wh1, wh0);
                    uint32_t a2 = cvt_f16x2(wg3, wg2);
                    uint32_t a3 = cvt_f16x2(wh3, wh2);

                    uint32_t b0, b1, b2, b3;
                    ldmatrix_x4_trans(b0, b1, b2, b3, ybase + (ks * 16) * (YSTR * 2));

                    mma16816(d10, d11, d12, d13, a0, a1, a2, a3, b0, b1);
                    mma16816(d20, d21, d22, d23, a0, a1, a2, a3, b2, b3);
                    mma16816(e0, e1, e2, e3, a0, a1, a2, a3, ONES, ONES);
                }

                if (sc + 1 < NSCU) STS_CHUNK(b ^ 1);
                if (sc + 2 < NSCU && tid == 0) {
                    spin_until(&g_ccnt[cb + sc + 2], NPROD);
                    __threadfence();
                }
                __syncthreads();
                if (sc + 2 < NSCU) LDG_CHUNK(sc + 2);
            }
#undef LDG_CHUNK
#undef STS_CHUNK

            int slot = s * 2 + half;
            float* p0 = &g_pnum[((size_t)slot * NT + r0) * NCLS];
            float* p1 = &g_pnum[((size_t)slot * NT + r1) * NCLS];
            *reinterpret_cast<float2*>(p0 + 2 * tg)     = make_float2(d10, d11);
            *reinterpret_cast<float2*>(p0 + 8 + 2 * tg) = make_float2(d20, d21);
            *reinterpret_cast<float2*>(p1 + 2 * tg)     = make_float2(d12, d13);
            *reinterpret_cast<float2*>(p1 + 8 + 2 * tg) = make_float2(d22, d23);
            if (tg == 0) {
                g_pden[(size_t)slot * NT + r0] = e0;
                g_pden[(size_t)slot * NT + r1] = e2;
            }
        }
    }
}

// ---------------- reduce: sum 16 slots, normalize, reset queue state ----------------
__global__ __launch_bounds__(128) void reduce_kernel(float* __restrict__ out) {
    int idx = blockIdx.x * 128 + threadIdx.x;     // 0 .. NT*4-1
    int i   = idx >> 2;
    int tg  = idx & 3;

    float4 n = make_float4(0, 0, 0, 0);
    float d = 0.f;
    #pragma unroll
    for (int sl = 0; sl < NSLOT; sl++) {
        float4 a = *reinterpret_cast<const float4*>(
            &g_pnum[((size_t)sl * NT + i) * NCLS + tg * 4]);
        n.x += a.x; n.y += a.y; n.z += a.z; n.w += a.w;
        d += g_pden[(size_t)sl * NT + i];
    }
    float inv = 1.0f / d;
    n.x *= inv; n.y *= inv; n.z *= inv; n.w *= inv;
    *reinterpret_cast<float4*>(out + (size_t)i * NCLS + tg * 4) = n;

    // reset ticket/flag state for next graph replay (stream-ordered before next launch)
    if (blockIdx.x == 0) {
        int tid = threadIdx.x;
        g_qrdy[tid] = 0;                  // 128 entries
        if (tid < 64) g_ccnt[tid] = 0;
        if (tid == 0) g_ticket = 0;
    }
}

// ---------------- launch ----------------
extern "C" void kernel_launch(void* const* d_in, const int* in_sizes, int n_in,
                              void* d_out, int out_size) {
    const float* xtr = (const float*)d_in[0];   // [16384, 512]
    const float* ytr = (const float*)d_in[1];   // [16384, 16]
    const float* xt  = (const float*)d_in[2];   // [8192, 512]
    const float* A   = (const float*)d_in[3];   // [512, 2]
    float* out = (float*)d_out;                 // [8192, 16]

    fused_kernel<<<GRID_FUSED, 128>>>(xtr, ytr, xt, A);
    reduce_kernel<<<NT * 4 / 128, 128>>>(out);  // 256 CTAs
}

// round 16
// speedup vs baseline: 2.0037x; 2.0037x over previous
#include <cuda_runtime.h>
#include <cuda_fp16.h>
#include <cstdint>

#define D     512
#define NTR   16384
#define NT    8192
#define NCLS  16

#define NSPLIT  8
#define JCHUNK  (NTR / NSPLIT)       // 2048
#define SCHUNK  256                  // j staged per buffer
#define NSC     (JCHUNK / SCHUNK)    // 8
#define KSTEPS  (SCHUNK / 16)        // 16 mma k-steps per staged chunk
#define MTILE   64                   // i rows per CTA (4 warps x 16)
#define YSTR    24                   // halves per padded ytr row (48B, conflict-free ldmatrix)

#define LOG2E  1.4426950408889634f
#define MS2    (-8.656170245333781f)   // -6 nats in log2 units, softmax-invariant shift

#define RPW       4                    // rows per warp in proj
#define PROJ_CTAS ((NT + NTR) / (8 * RPW))   // 768
#define PREP_CTAS (NTR / 256)                // 64

// ---------------- device scratch ----------------
__device__ float2 g_q[NT];          // q pre-scaled by log2(e)
__device__ float2 g_k[NTR];
__device__ uint4  g_y16[NTR * 2];   // fp16 ytr, 32B per row
__device__ float  g_pnum[NSPLIT * NT * NCLS];
__device__ float  g_pden[NSPLIT * NT];
__device__ int    g_cnt[NT / MTILE];   // per-i-tile completion counters (self-resetting)

// ---------------- helpers ----------------
__device__ __forceinline__ float ex2f(float x) {
    float r; asm("ex2.approx.ftz.f32 %0, %1;" : "=f"(r) : "f"(x)); return r;
}
__device__ __forceinline__ uint32_t cvt_f16x2(float hi, float lo) {
    uint32_t r; asm("cvt.rn.f16x2.f32 %0, %1, %2;" : "=r"(r) : "f"(hi), "f"(lo)); return r;
}
__device__ __forceinline__ uint32_t smem_u32(const void* p) {
    uint32_t a;
    asm("{ .reg .u64 t; cvta.to.shared.u64 t, %1; cvt.u32.u64 %0, t; }" : "=r"(a) : "l"(p));
    return a;
}
__device__ __forceinline__ void ldmatrix_x4_trans(uint32_t& r0, uint32_t& r1,
                                                  uint32_t& r2, uint32_t& r3,
                                                  uint32_t addr) {
    asm volatile("ldmatrix.sync.aligned.m8n8.x4.trans.shared.b16 {%0,%1,%2,%3}, [%4];"
                 : "=r"(r0), "=r"(r1), "=r"(r2), "=r"(r3) : "r"(addr));
}
__device__ __forceinline__ void mma16816(float& c0, float& c1, float& c2, float& c3,
                                         uint32_t a0, uint32_t a1, uint32_t a2, uint32_t a3,
                                         uint32_t b0, uint32_t b1) {
    asm volatile("mma.sync.aligned.m16n8k16.row.col.f32.f16.f16.f32 "
                 "{%0,%1,%2,%3}, {%4,%5,%6,%7}, {%8,%9}, {%0,%1,%2,%3};"
                 : "+f"(c0), "+f"(c1), "+f"(c2), "+f"(c3)
                 : "r"(a0), "r"(a1), "r"(a2), "r"(a3), "r"(b0), "r"(b1));
}

// ---------------- kernel 1: fused projections + ytr->fp16 conversion (round-8 body) ----------------
__global__ __launch_bounds__(256) void proj_prep_kernel(const float* __restrict__ xt,
                                                        const float* __restrict__ xtr,
                                                        const float* __restrict__ A,
                                                        const float* __restrict__ ytr) {
    int tid = threadIdx.x;

    if (blockIdx.x >= PROJ_CTAS) {
        // ---- prep branch: ytr -> fp16 ----
        int row = (blockIdx.x - PROJ_CTAS) * 256 + tid;
        const float4* src = reinterpret_cast<const float4*>(ytr + (size_t)row * NCLS);
        float4 v0 = src[0], v1 = src[1], v2 = src[2], v3 = src[3];
        uint4 o0, o1;
        o0.x = cvt_f16x2(v0.y, v0.x); o0.y = cvt_f16x2(v0.w, v0.z);
        o0.z = cvt_f16x2(v1.y, v1.x); o0.w = cvt_f16x2(v1.w, v1.z);
        o1.x = cvt_f16x2(v2.y, v2.x); o1.y = cvt_f16x2(v2.w, v2.z);
        o1.z = cvt_f16x2(v3.y, v3.x); o1.w = cvt_f16x2(v3.w, v3.z);
        g_y16[row * 2]     = o0;
        g_y16[row * 2 + 1] = o1;
        return;
    }

    // ---- proj branch: q = (xt@A)*log2e, k = xtr@A ----
    // A staged transposed so the per-lane column slice hits bank == lane (conflict-free).
    __shared__ float sA0t[D], sA1t[D];
    #pragma unroll
    for (int c = tid; c < D; c += 256) {
        float2 a = reinterpret_cast<const float2*>(A)[c];
        int idx = (c >> 7) * 128 + (c & 3) * 32 + ((c >> 2) & 31);
        sA0t[idx] = a.x; sA1t[idx] = a.y;
    }
    __syncthreads();

    int warp = tid >> 5;
    int lane = tid & 31;
    int row0 = blockIdx.x * (8 * RPW) + warp * RPW;

    const float* src;  float2* dst;  float scale;
    if (row0 < NT) { src = xt;  dst = g_q; scale = LOG2E; }
    else           { src = xtr; dst = g_k; scale = 1.0f;  row0 -= NT; }

    // hoist this lane's A slice into registers (reused across RPW rows)
    float a0[16], a1[16];
    #pragma unroll
    for (int it = 0; it < 4; it++) {
        #pragma unroll
        for (int u = 0; u < 4; u++) {
            int idx = it * 128 + u * 32 + lane;
            a0[it * 4 + u] = sA0t[idx];
            a1[it * 4 + u] = sA1t[idx];
        }
    }

    #pragma unroll
    for (int r = 0; r < RPW; r++) {
        const float4* xr4 = reinterpret_cast<const float4*>(src + (size_t)(row0 + r) * D);
        float4 x0 = xr4[lane];
        float4 x1 = xr4[32 + lane];
        float4 x2 = xr4[64 + lane];
        float4 x3 = xr4[96 + lane];

        float s0, s1;
        s0 =      x0.x * a0[0];            s1 =      x0.x * a1[0];
        s0 = fmaf(x0.y, a0[1],  s0);       s1 = fmaf(x0.y, a1[1],  s1);
        s0 = fmaf(x0.z, a0[2],  s0);       s1 = fmaf(x0.z, a1[2],  s1);
        s0 = fmaf(x0.w, a0[3],  s0);       s1 = fmaf(x0.w, a1[3],  s1);
        s0 = fmaf(x1.x, a0[4],  s0);       s1 = fmaf(x1.x, a1[4],  s1);
        s0 = fmaf(x1.y, a0[5],  s0);       s1 = fmaf(x1.y, a1[5],  s1);
        s0 = fmaf(x1.z, a0[6],  s0);       s1 = fmaf(x1.z, a1[6],  s1);
        s0 = fmaf(x1.w, a0[7],  s0);       s1 = fmaf(x1.w, a1[7],  s1);
        s0 = fmaf(x2.x, a0[8],  s0);       s1 = fmaf(x2.x, a1[8],  s1);
        s0 = fmaf(x2.y, a0[9],  s0);       s1 = fmaf(x2.y, a1[9],  s1);
        s0 = fmaf(x2.z, a0[10], s0);       s1 = fmaf(x2.z, a1[10], s1);
        s0 = fmaf(x2.w, a0[11], s0);       s1 = fmaf(x2.w, a1[11], s1);
        s0 = fmaf(x3.x, a0[12], s0);       s1 = fmaf(x3.x, a1[12], s1);
        s0 = fmaf(x3.y, a0[13], s0);       s1 = fmaf(x3.y, a1[13], s1);
        s0 = fmaf(x3.z, a0[14], s0);       s1 = fmaf(x3.z, a1[14], s1);
        s0 = fmaf(x3.w, a0[15], s0);       s1 = fmaf(x3.w, a1[15], s1);

        #pragma unroll
        for (int off = 16; off > 0; off >>= 1) {
            s0 += __shfl_xor_sync(0xFFFFFFFFu, s0, off);
            s1 += __shfl_xor_sync(0xFFFFFFFFu, s1, off);
        }
        if (lane == 0) dst[row0 + r] = make_float2(s0 * scale, s1 * scale);
    }
}

// ---------------- kernel 2: attn (round-4 body) + fused last-CTA reduce ----------------
__global__ __launch_bounds__(128, 7) void attn_kernel(float* __restrict__ out) {
    __shared__ float2 sk[2][SCHUNK];                         // 2 x 2KB
    __shared__ __align__(16) __half sy[2][SCHUNK * YSTR];    // 2 x 12KB (48B rows)
    __shared__ int s_last;

    int tid  = threadIdx.x;
    int wid  = tid >> 5;
    int lane = tid & 31;
    int g    = lane >> 2;
    int tg   = lane & 3;
    int split = blockIdx.y;
    int r0 = blockIdx.x * MTILE + wid * 16 + g;
    int r1 = r0 + 8;
    int j0 = split * JCHUNK;

    float2 qg = g_q[r0];
    float2 qh = g_q[r1];

    // accumulators: classes n0-7, n8-15, denominator (ones-column MMA)
    float d10 = 0, d11 = 0, d12 = 0, d13 = 0;
    float d20 = 0, d21 = 0, d22 = 0, d23 = 0;
    float e0 = 0, e1 = 0, e2 = 0, e3 = 0;
    const uint32_t ONES = 0x3C003C00u;

    // prefetch registers for staging
    float4 pk;  uint4 py0, py1, py2, py3;

#define LDG_CHUNK(sc) do {                                                   \
        int jb = j0 + (sc) * SCHUNK;                                         \
        pk = reinterpret_cast<const float4*>(g_k)[(jb >> 1) + tid];          \
        int rr = (jb + 2 * tid) * 2;                                         \
        py0 = g_y16[rr]; py1 = g_y16[rr + 1];                                \
        py2 = g_y16[rr + 2]; py3 = g_y16[rr + 3];                            \
    } while (0)

#define STS_CHUNK(b) do {                                                    \
        reinterpret_cast<float4*>(sk[b])[tid] = pk;                          \
        uint4* dr0 = reinterpret_cast<uint4*>(&sy[b][(2 * tid) * YSTR]);     \
        dr0[0] = py0; dr0[1] = py1;                                          \
        uint4* dr1 = reinterpret_cast<uint4*>(&sy[b][(2 * tid + 1) * YSTR]); \
        dr1[0] = py2; dr1[1] = py3;                                          \
    } while (0)

    LDG_CHUNK(0);
    STS_CHUNK(0);
    LDG_CHUNK(1);
    __syncthreads();

    for (int sc = 0; sc < NSC; sc++) {
        int b = sc & 1;
        const float4* k4 = reinterpret_cast<const float4*>(sk[b]);
        uint32_t ybase = smem_u32(&sy[b][(lane & 15) * YSTR]) + (lane >> 4) * 16;

        #pragma unroll 4
        for (int ks = 0; ks < KSTEPS; ks++) {
            // k values: j = ks*16 + {2tg,2tg+1} and +8 (broadcast LDS)
            float4 ka = k4[ks * 8 + tg];
            float4 kb = k4[ks * 8 + 4 + tg];

            float wg0 = ex2f(fmaf(qg.x, ka.x, fmaf(qg.y, ka.y, MS2)));
            float wg1 = ex2f(fmaf(qg.x, ka.z, fmaf(qg.y, ka.w, MS2)));
            float wg2 = ex2f(fmaf(qg.x, kb.x, fmaf(qg.y, kb.y, MS2)));
            float wg3 = ex2f(fmaf(qg.x, kb.z, fmaf(qg.y, kb.w, MS2)));
            float wh0 = ex2f(fmaf(qh.x, ka.x, fmaf(qh.y, ka.y, MS2)));
            float wh1 = ex2f(fmaf(qh.x, ka.z, fmaf(qh.y, ka.w, MS2)));
            float wh2 = ex2f(fmaf(qh.x, kb.x, fmaf(qh.y, kb.y, MS2)));
            float wh3 = ex2f(fmaf(qh.x, kb.z, fmaf(qh.y, kb.w, MS2)));

            uint32_t a0 = cvt_f16x2(wg1, wg0);
            uint32_t a1 = cvt_f16x2(wh1, wh0);
            uint32_t a2 = cvt_f16x2(wg3, wg2);
            uint32_t a3 = cvt_f16x2(wh3, wh2);

            uint32_t b0, b1, b2, b3;
            ldmatrix_x4_trans(b0, b1, b2, b3, ybase + (ks * 16) * (YSTR * 2));

            mma16816(d10, d11, d12, d13, a0, a1, a2, a3, b0, b1);   // classes 0-7
            mma16816(d20, d21, d22, d23, a0, a1, a2, a3, b2, b3);   // classes 8-15
            mma16816(e0, e1, e2, e3, a0, a1, a2, a3, ONES, ONES);   // denominator
        }

        if (sc + 1 < NSC) {
            STS_CHUNK(b ^ 1);
            if (sc + 2 < NSC) LDG_CHUNK(sc + 2);
        }
        __syncthreads();
    }

    // ---- write partials ----
    float* p0 = &g_pnum[((size_t)split * NT + r0) * NCLS];
    float* p1 = &g_pnum[((size_t)split * NT + r1) * NCLS];
    *reinterpret_cast<float2*>(p0 + 2 * tg)     = make_float2(d10, d11);
    *reinterpret_cast<float2*>(p0 + 8 + 2 * tg) = make_float2(d20, d21);
    *reinterpret_cast<float2*>(p1 + 2 * tg)     = make_float2(d12, d13);
    *reinterpret_cast<float2*>(p1 + 8 + 2 * tg) = make_float2(d22, d23);
    if (tg == 0) {
        g_pden[(size_t)split * NT + r0] = e0;
        g_pden[(size_t)split * NT + r1] = e2;
    }

    // ---- last-arriving CTA for this i-tile reduces all 8 splits ----
    __syncthreads();                       // all partial writes issued (CTA scope)
    if (tid == 0) {
        __threadfence();                   // release: cumulative over CTA-prior writes
        int old = atomicAdd(&g_cnt[blockIdx.x], 1);
        s_last = (old == NSPLIT - 1) ? 1 : 0;
    }
    __syncthreads();
    if (s_last) {
        __threadfence();                   // acquire side
        // 64 rows x 4 class-quads = 256 items; 128 threads, 2 each
        #pragma unroll
        for (int it = 0; it < 2; it++) {
            int idx = tid + it * 128;
            int row = blockIdx.x * MTILE + (idx >> 2);
            int tq  = idx & 3;
            float4 n = make_float4(0, 0, 0, 0);
            float dsum = 0.f;
            #pragma unroll
            for (int s = 0; s < NSPLIT; s++) {
                float4 a = *reinterpret_cast<const float4*>(
                    &g_pnum[((size_t)s * NT + row) * NCLS + tq * 4]);
                n.x += a.x; n.y += a.y; n.z += a.z; n.w += a.w;
                dsum += g_pden[(size_t)s * NT + row];
            }
            float inv = 1.0f / dsum;
            n.x *= inv; n.y *= inv; n.z *= inv; n.w *= inv;
            *reinterpret_cast<float4*>(out + (size_t)row * NCLS + tq * 4) = n;
        }
        if (tid == 0) g_cnt[blockIdx.x] = 0;   // reset for next graph replay
    }
#undef LDG_CHUNK
#undef STS_CHUNK
}

// ---------------- launch ----------------
extern "C" void kernel_launch(void* const* d_in, const int* in_sizes, int n_in,
                              void* d_out, int out_size) {
    const float* xtr = (const float*)d_in[0];   // [16384, 512]
    const float* ytr = (const float*)d_in[1];   // [16384, 16]
    const float* xt  = (const float*)d_in[2];   // [8192, 512]
    const float* A   = (const float*)d_in[3];   // [512, 2]
    float* out = (float*)d_out;                 // [8192, 16]

    proj_prep_kernel<<<PROJ_CTAS + PREP_CTAS, 256>>>(xt, xtr, A, ytr);

    dim3 grid(NT / MTILE, NSPLIT);               // 128 x 8 = 1024 CTAs
    attn_kernel<<<grid, 128>>>(out);
}

// round 17
// speedup vs baseline: 2.2600x; 1.1279x over previous
#include <cuda_runtime.h>
#include <cuda_fp16.h>
#include <cstdint>

#define D     512
#define NTR   16384
#define NT    8192
#define NCLS  16

#define NSPLIT  16
#define JCHUNK  (NTR / NSPLIT)       // 1024
#define SCHUNK  256                  // j staged per buffer
#define NSC     (JCHUNK / SCHUNK)    // 4
#define KSTEPS  (SCHUNK / 16)        // 16 mma k-steps per staged chunk
#define MTILE   128                  // i rows per CTA (4 warps x 32)
#define YSTR    24                   // halves per padded ytr row (48B, conflict-free ldmatrix)

#define LOG2E  1.4426950408889634f
#define MS2    (-8.656170245333781f)   // -6 nats in log2 units, softmax-invariant shift

#define RPW       4                    // rows per warp in proj
#define PROJ_CTAS ((NT + NTR) / (8 * RPW))   // 768
#define PREP_CTAS (NTR / 256)                // 64

// ---------------- device scratch ----------------
__device__ float2 g_q[NT];          // q pre-scaled by log2(e)
__device__ float2 g_k[NTR];
__device__ uint4  g_y16[NTR * 2];   // fp16 ytr, 32B per row
__device__ float  g_pnum[NSPLIT * NT * NCLS];
__device__ float  g_pden[NSPLIT * NT];
__device__ int    g_cnt[NT / MTILE];   // per-i-tile completion counters (self-resetting)

// ---------------- helpers ----------------
__device__ __forceinline__ float ex2f(float x) {
    float r; asm("ex2.approx.ftz.f32 %0, %1;" : "=f"(r) : "f"(x)); return r;
}
__device__ __forceinline__ uint32_t cvt_f16x2(float hi, float lo) {
    uint32_t r; asm("cvt.rn.f16x2.f32 %0, %1, %2;" : "=r"(r) : "f"(hi), "f"(lo)); return r;
}
__device__ __forceinline__ uint32_t smem_u32(const void* p) {
    uint32_t a;
    asm("{ .reg .u64 t; cvta.to.shared.u64 t, %1; cvt.u32.u64 %0, t; }" : "=r"(a) : "l"(p));
    return a;
}
__device__ __forceinline__ void ldmatrix_x4_trans(uint32_t& r0, uint32_t& r1,
                                                  uint32_t& r2, uint32_t& r3,
                                                  uint32_t addr) {
    asm volatile("ldmatrix.sync.aligned.m8n8.x4.trans.shared.b16 {%0,%1,%2,%3}, [%4];"
                 : "=r"(r0), "=r"(r1), "=r"(r2), "=r"(r3) : "r"(addr));
}
__device__ __forceinline__ void mma16816(float& c0, float& c1, float& c2, float& c3,
                                         uint32_t a0, uint32_t a1, uint32_t a2, uint32_t a3,
                                         uint32_t b0, uint32_t b1) {
    asm volatile("mma.sync.aligned.m16n8k16.row.col.f32.f16.f16.f32 "
                 "{%0,%1,%2,%3}, {%4,%5,%6,%7}, {%8,%9}, {%0,%1,%2,%3};"
                 : "+f"(c0), "+f"(c1), "+f"(c2), "+f"(c3)
                 : "r"(a0), "r"(a1), "r"(a2), "r"(a3), "r"(b0), "r"(b1));
}

// ---------------- kernel 1: fused projections + ytr->fp16 conversion (round-8 body) ----------------
__global__ __launch_bounds__(256) void proj_prep_kernel(const float* __restrict__ xt,
                                                        const float* __restrict__ xtr,
                                                        const float* __restrict__ A,
                                                        const float* __restrict__ ytr) {
    int tid = threadIdx.x;

    if (blockIdx.x >= PROJ_CTAS) {
        // ---- prep branch: ytr -> fp16 ----
        int row = (blockIdx.x - PROJ_CTAS) * 256 + tid;
        const float4* src = reinterpret_cast<const float4*>(ytr + (size_t)row * NCLS);
        float4 v0 = src[0], v1 = src[1], v2 = src[2], v3 = src[3];
        uint4 o0, o1;
        o0.x = cvt_f16x2(v0.y, v0.x); o0.y = cvt_f16x2(v0.w, v0.z);
        o0.z = cvt_f16x2(v1.y, v1.x); o0.w = cvt_f16x2(v1.w, v1.z);
        o1.x = cvt_f16x2(v2.y, v2.x); o1.y = cvt_f16x2(v2.w, v2.z);
        o1.z = cvt_f16x2(v3.y, v3.x); o1.w = cvt_f16x2(v3.w, v3.z);
        g_y16[row * 2]     = o0;
        g_y16[row * 2 + 1] = o1;
        return;
    }

    // ---- proj branch: q = (xt@A)*log2e, k = xtr@A ----
    __shared__ float sA0t[D], sA1t[D];
    #pragma unroll
    for (int c = tid; c < D; c += 256) {
        float2 a = reinterpret_cast<const float2*>(A)[c];
        int idx = (c >> 7) * 128 + (c & 3) * 32 + ((c >> 2) & 31);
        sA0t[idx] = a.x; sA1t[idx] = a.y;
    }
    __syncthreads();

    int warp = tid >> 5;
    int lane = tid & 31;
    int row0 = blockIdx.x * (8 * RPW) + warp * RPW;

    const float* src;  float2* dst;  float scale;
    if (row0 < NT) { src = xt;  dst = g_q; scale = LOG2E; }
    else           { src = xtr; dst = g_k; scale = 1.0f;  row0 -= NT; }

    float a0[16], a1[16];
    #pragma unroll
    for (int it = 0; it < 4; it++) {
        #pragma unroll
        for (int u = 0; u < 4; u++) {
            int idx = it * 128 + u * 32 + lane;
            a0[it * 4 + u] = sA0t[idx];
            a1[it * 4 + u] = sA1t[idx];
        }
    }

    #pragma unroll
    for (int r = 0; r < RPW; r++) {
        const float4* xr4 = reinterpret_cast<const float4*>(src + (size_t)(row0 + r) * D);
        float4 x0 = xr4[lane];
        float4 x1 = xr4[32 + lane];
        float4 x2 = xr4[64 + lane];
        float4 x3 = xr4[96 + lane];

        float s0, s1;
        s0 =      x0.x * a0[0];            s1 =      x0.x * a1[0];
        s0 = fmaf(x0.y, a0[1],  s0);       s1 = fmaf(x0.y, a1[1],  s1);
        s0 = fmaf(x0.z, a0[2],  s0);       s1 = fmaf(x0.z, a1[2],  s1);
        s0 = fmaf(x0.w, a0[3],  s0);       s1 = fmaf(x0.w, a1[3],  s1);
        s0 = fmaf(x1.x, a0[4],  s0);       s1 = fmaf(x1.x, a1[4],  s1);
        s0 = fmaf(x1.y, a0[5],  s0);       s1 = fmaf(x1.y, a1[5],  s1);
        s0 = fmaf(x1.z, a0[6],  s0);       s1 = fmaf(x1.z, a1[6],  s1);
        s0 = fmaf(x1.w, a0[7],  s0);       s1 = fmaf(x1.w, a1[7],  s1);
        s0 = fmaf(x2.x, a0[8],  s0);       s1 = fmaf(x2.x, a1[8],  s1);
        s0 = fmaf(x2.y, a0[9],  s0);       s1 = fmaf(x2.y, a1[9],  s1);
        s0 = fmaf(x2.z, a0[10], s0);       s1 = fmaf(x2.z, a1[10], s1);
        s0 = fmaf(x2.w, a0[11], s0);       s1 = fmaf(x2.w, a1[11], s1);
        s0 = fmaf(x3.x, a0[12], s0);       s1 = fmaf(x3.x, a1[12], s1);
        s0 = fmaf(x3.y, a0[13], s0);       s1 = fmaf(x3.y, a1[13], s1);
        s0 = fmaf(x3.z, a0[14], s0);       s1 = fmaf(x3.z, a1[14], s1);
        s0 = fmaf(x3.w, a0[15], s0);       s1 = fmaf(x3.w, a1[15], s1);

        #pragma unroll
        for (int off = 16; off > 0; off >>= 1) {
            s0 += __shfl_xor_sync(0xFFFFFFFFu, s0, off);
            s1 += __shfl_xor_sync(0xFFFFFFFFu, s1, off);
        }
        if (lane == 0) dst[row0 + r] = make_float2(s0 * scale, s1 * scale);
    }
}

// ---------------- kernel 2: attn, 32 i-rows per warp (shared B frags) + fused reduce ----------------
__global__ __launch_bounds__(128, 5) void attn_kernel(float* __restrict__ out) {
    __shared__ float2 sk[2][SCHUNK];                         // 2 x 2KB
    __shared__ __align__(16) __half sy[2][SCHUNK * YSTR];    // 2 x 12KB (48B rows)
    __shared__ int s_last;

    int tid  = threadIdx.x;
    int wid  = tid >> 5;
    int lane = tid & 31;
    int g    = lane >> 2;
    int tg   = lane & 3;
    int split = blockIdx.y;
    int base = blockIdx.x * MTILE + wid * 32;
    int j0 = split * JCHUNK;

    // two m16 tiles per warp: rows [base, base+16), [base+16, base+32)
    float2 qg0 = g_q[base + g];
    float2 qh0 = g_q[base + g + 8];
    float2 qg1 = g_q[base + 16 + g];
    float2 qh1 = g_q[base + 24 + g];

    // accumulators: per tile {classes 0-7, 8-15, denominator}
    float d10 = 0, d11 = 0, d12 = 0, d13 = 0;
    float d20 = 0, d21 = 0, d22 = 0, d23 = 0;
    float e0 = 0, e1 = 0, e2 = 0, e3 = 0;
    float f10 = 0, f11 = 0, f12 = 0, f13 = 0;
    float f20 = 0, f21 = 0, f22 = 0, f23 = 0;
    float h0 = 0, h1 = 0, h2 = 0, h3 = 0;
    const uint32_t ONES = 0x3C003C00u;

    float4 pk;  uint4 py0, py1, py2, py3;

#define LDG_CHUNK(sc) do {                                                   \
        int jb = j0 + (sc) * SCHUNK;                                         \
        pk = reinterpret_cast<const float4*>(g_k)[(jb >> 1) + tid];          \
        int rr = (jb + 2 * tid) * 2;                                         \
        py0 = g_y16[rr]; py1 = g_y16[rr + 1];                                \
        py2 = g_y16[rr + 2]; py3 = g_y16[rr + 3];                            \
    } while (0)

#define STS_CHUNK(b) do {                                                    \
        reinterpret_cast<float4*>(sk[b])[tid] = pk;                          \
        uint4* dr0 = reinterpret_cast<uint4*>(&sy[b][(2 * tid) * YSTR]);     \
        dr0[0] = py0; dr0[1] = py1;                                          \
        uint4* dr1 = reinterpret_cast<uint4*>(&sy[b][(2 * tid + 1) * YSTR]); \
        dr1[0] = py2; dr1[1] = py3;                                          \
    } while (0)

    LDG_CHUNK(0);
    STS_CHUNK(0);
    LDG_CHUNK(1);
    __syncthreads();

    for (int sc = 0; sc < NSC; sc++) {
        int b = sc & 1;
        const float4* k4 = reinterpret_cast<const float4*>(sk[b]);
        uint32_t ybase = smem_u32(&sy[b][(lane & 15) * YSTR]) + (lane >> 4) * 16;

        #pragma unroll 2
        for (int ks = 0; ks < KSTEPS; ks++) {
            float4 ka = k4[ks * 8 + tg];
            float4 kb = k4[ks * 8 + 4 + tg];

            // tile 0 weights
            float w0 = ex2f(fmaf(qg0.x, ka.x, fmaf(qg0.y, ka.y, MS2)));
            float w1 = ex2f(fmaf(qg0.x, ka.z, fmaf(qg0.y, ka.w, MS2)));
            float w2 = ex2f(fmaf(qg0.x, kb.x, fmaf(qg0.y, kb.y, MS2)));
            float w3 = ex2f(fmaf(qg0.x, kb.z, fmaf(qg0.y, kb.w, MS2)));
            float w4 = ex2f(fmaf(qh0.x, ka.x, fmaf(qh0.y, ka.y, MS2)));
            float w5 = ex2f(fmaf(qh0.x, ka.z, fmaf(qh0.y, ka.w, MS2)));
            float w6 = ex2f(fmaf(qh0.x, kb.x, fmaf(qh0.y, kb.y, MS2)));
            float w7 = ex2f(fmaf(qh0.x, kb.z, fmaf(qh0.y, kb.w, MS2)));
            uint32_t a0 = cvt_f16x2(w1, w0);
            uint32_t a1 = cvt_f16x2(w5, w4);
            uint32_t a2 = cvt_f16x2(w3, w2);
            uint32_t a3 = cvt_f16x2(w7, w6);

            // tile 1 weights
            float v0 = ex2f(fmaf(qg1.x, ka.x, fmaf(qg1.y, ka.y, MS2)));
            float v1 = ex2f(fmaf(qg1.x, ka.z, fmaf(qg1.y, ka.w, MS2)));
            float v2 = ex2f(fmaf(qg1.x, kb.x, fmaf(qg1.y, kb.y, MS2)));
            float v3 = ex2f(fmaf(qg1.x, kb.z, fmaf(qg1.y, kb.w, MS2)));
            float v4 = ex2f(fmaf(qh1.x, ka.x, fmaf(qh1.y, ka.y, MS2)));
            float v5 = ex2f(fmaf(qh1.x, ka.z, fmaf(qh1.y, ka.w, MS2)));
            float v6 = ex2f(fmaf(qh1.x, kb.x, fmaf(qh1.y, kb.y, MS2)));
            float v7 = ex2f(fmaf(qh1.x, kb.z, fmaf(qh1.y, kb.w, MS2)));
            uint32_t a4 = cvt_f16x2(v1, v0);
            uint32_t a5 = cvt_f16x2(v5, v4);
            uint32_t a6 = cvt_f16x2(v3, v2);
            uint32_t a7 = cvt_f16x2(v7, v6);

            // ONE ldmatrix feeds both tiles
            uint32_t b0, b1, b2, b3;
            ldmatrix_x4_trans(b0, b1, b2, b3, ybase + (ks * 16) * (YSTR * 2));

            mma16816(d10, d11, d12, d13, a0, a1, a2, a3, b0, b1);
            mma16816(d20, d21, d22, d23, a0, a1, a2, a3, b2, b3);
            mma16816(e0, e1, e2, e3, a0, a1, a2, a3, ONES, ONES);
            mma16816(f10, f11, f12, f13, a4, a5, a6, a7, b0, b1);
            mma16816(f20, f21, f22, f23, a4, a5, a6, a7, b2, b3);
            mma16816(h0, h1, h2, h3, a4, a5, a6, a7, ONES, ONES);
        }

        if (sc + 1 < NSC) {
            STS_CHUNK(b ^ 1);
            if (sc + 2 < NSC) LDG_CHUNK(sc + 2);
        }
        __syncthreads();
    }

    // ---- write partials (slot = split) ----
    {
        int r0 = base + g, r1 = r0 + 8, r2 = r0 + 16, r3 = r0 + 24;
        float* p0 = &g_pnum[((size_t)split * NT + r0) * NCLS];
        float* p1 = &g_pnum[((size_t)split * NT + r1) * NCLS];
        float* p2 = &g_pnum[((size_t)split * NT + r2) * NCLS];
        float* p3 = &g_pnum[((size_t)split * NT + r3) * NCLS];
        *reinterpret_cast<float2*>(p0 + 2 * tg)     = make_float2(d10, d11);
        *reinterpret_cast<float2*>(p0 + 8 + 2 * tg) = make_float2(d20, d21);
        *reinterpret_cast<float2*>(p1 + 2 * tg)     = make_float2(d12, d13);
        *reinterpret_cast<float2*>(p1 + 8 + 2 * tg) = make_float2(d22, d23);
        *reinterpret_cast<float2*>(p2 + 2 * tg)     = make_float2(f10, f11);
        *reinterpret_cast<float2*>(p2 + 8 + 2 * tg) = make_float2(f20, f21);
        *reinterpret_cast<float2*>(p3 + 2 * tg)     = make_float2(f12, f13);
        *reinterpret_cast<float2*>(p3 + 8 + 2 * tg) = make_float2(f22, f23);
        if (tg == 0) {
            g_pden[(size_t)split * NT + r0] = e0;
            g_pden[(size_t)split * NT + r1] = e2;
            g_pden[(size_t)split * NT + r2] = h0;
            g_pden[(size_t)split * NT + r3] = h2;
        }
    }

    // ---- last-arriving CTA for this i-tile reduces all 16 splits ----
    __syncthreads();
    if (tid == 0) {
        __threadfence();
        int old = atomicAdd(&g_cnt[blockIdx.x], 1);
        s_last = (old == NSPLIT - 1) ? 1 : 0;
    }
    __syncthreads();
    if (s_last) {
        __threadfence();
        // 128 rows x 4 class-quads = 512 items; 128 threads, 4 each
        #pragma unroll
        for (int it = 0; it < 4; it++) {
            int idx = tid + it * 128;
            int row = blockIdx.x * MTILE + (idx >> 2);
            int tq  = idx & 3;
            float4 n = make_float4(0, 0, 0, 0);
            float dsum = 0.f;
            #pragma unroll
            for (int s = 0; s < NSPLIT; s++) {
                float4 a = *reinterpret_cast<const float4*>(
                    &g_pnum[((size_t)s * NT + row) * NCLS + tq * 4]);
                n.x += a.x; n.y += a.y; n.z += a.z; n.w += a.w;
                dsum += g_pden[(size_t)s * NT + row];
            }
            float inv = 1.0f / dsum;
            n.x *= inv; n.y *= inv; n.z *= inv; n.w *= inv;
            *reinterpret_cast<float4*>(out + (size_t)row * NCLS + tq * 4) = n;
        }
        if (tid == 0) g_cnt[blockIdx.x] = 0;   // reset for next graph replay
    }
#undef LDG_CHUNK
#undef STS_CHUNK
}

// ---------------- launch ----------------
extern "C" void kernel_launch(void* const* d_in, const int* in_sizes, int n_in,
                              void* d_out, int out_size) {
    const float* xtr = (const float*)d_in[0];   // [16384, 512]
    const float* ytr = (const float*)d_in[1];   // [16384, 16]
    const float* xt  = (const float*)d_in[2];   // [8192, 512]
    const float* A   = (const float*)d_in[3];   // [512, 2]
    float* out = (float*)d_out;                 // [8192, 16]

    proj_prep_kernel<<<PROJ_CTAS + PREP_CTAS, 256>>>(xt, xtr, A, ytr);

    dim3 grid(NT / MTILE, NSPLIT);               // 64 x 16 = 1024 CTAs
    attn_kernel<<<grid, 128>>>(out);
}